// round 17
// baseline (speedup 1.0000x reference)
#include <cuda_runtime.h>
#include <cuda_fp16.h>
#include <cstdint>

#define NHEAD 12
#define HD 64
#define NTOK 512
#define NBATCH 32
#define DIM 768
#define MTOK (NBATCH*NTOK)
#define QKV_N (3*DIM)
#define ATTN_SCALE 0.125f

__device__ __half g_q[(size_t)NBATCH*NHEAD*NTOK*HD];
__device__ __half g_k[(size_t)NBATCH*NHEAD*NTOK*HD];
__device__ __half g_v[(size_t)NBATCH*NHEAD*NTOK*HD];
__device__ float  g_biasp[(size_t)NHEAD*NTOK*NTOK];  // c-frag layout
__device__ __half g_attnout[(size_t)MTOK*DIM];
__device__ __half g_xr[(size_t)MTOK*DIM];
__device__ __half g_wr_qkv[(size_t)QKV_N*DIM];
__device__ __half g_wr_proj[(size_t)DIM*DIM];

__device__ __forceinline__ uint32_t pack_h2(float lo, float hi){
    __half2 h = __floats2half2_rn(lo, hi);
    return *(uint32_t*)&h;
}
__device__ __forceinline__ void mma_f16(float* c, const uint32_t* a, const uint32_t* b){
    asm volatile("mma.sync.aligned.m16n8k16.row.col.f32.f16.f16.f32 "
        "{%0,%1,%2,%3}, {%4,%5,%6,%7}, {%8,%9}, {%0,%1,%2,%3};"
        : "+f"(c[0]),"+f"(c[1]),"+f"(c[2]),"+f"(c[3])
        : "r"(a[0]),"r"(a[1]),"r"(a[2]),"r"(a[3]),"r"(b[0]),"r"(b[1]));
}
__device__ __forceinline__ uint32_t smem_addr_of(const void* p){
    return (uint32_t)__cvta_generic_to_shared(p);
}
__device__ __forceinline__ void cp_async16(uint32_t dst, const void* src){
    asm volatile("cp.async.cg.shared.global [%0], [%1], 16;" :: "r"(dst), "l"(src));
}
__device__ __forceinline__ void cp_commit(){
    asm volatile("cp.async.commit_group;");
}
template<int N> __device__ __forceinline__ void cp_wait(){
    asm volatile("cp.async.wait_group %0;" :: "n"(N));
}
__device__ __forceinline__ void ldsm_x4(uint32_t* r, uint32_t addr){
    asm volatile("ldmatrix.sync.aligned.m8n8.x4.shared.b16 {%0,%1,%2,%3}, [%4];"
        : "=r"(r[0]),"=r"(r[1]),"=r"(r[2]),"=r"(r[3]) : "r"(addr));
}

// ---- float -> half copy ----
__global__ void half_copy_kernel(const float* __restrict__ src,
                                 __half* __restrict__ dst, int n4)
{
    int i = blockIdx.x*256 + threadIdx.x;
    if (i < n4) {
        float4 v = *(const float4*)&src[i*4];
        uint2 o;
        o.x = pack_h2(v.x, v.y);
        o.y = pack_h2(v.z, v.w);
        *(uint2*)(dst + (size_t)i*4) = o;
    }
}

// ---- bias gather into c-fragment layout ----
__global__ void bias_gather_kernel(const float* __restrict__ table,
                                   const int* __restrict__ idx)
{
    int e = blockIdx.x*256 + threadIdx.x;
    int rt=e>>13, kt=(e>>10)&7, nt=(e>>7)&7, lane=(e>>2)&31, reg=e&3;
    int g=lane>>2, l=lane&3;
    int row = rt*16 + g + 8*(reg>>1);
    int col = kt*64 + nt*8 + 2*l + (reg&1);
    int id = idx[row*NTOK + col];
    const float* t = table + (size_t)id*NHEAD;
#pragma unroll
    for (int h=0; h<NHEAD; h++)
        g_biasp[(size_t)h*262144 + e] = t[h];
}

// ---- FP16 GEMM: BM=128, BN=256, warp tile 32x128, 3-stage cp.async ----
// Smem tile row: 128 B; byte = row*128 + ((c ^ (row&7))<<4).
template<int MODE>
__global__ __launch_bounds__(256,1)
void gemm_f16_kernel(const float* __restrict__ biasv, float* __restrict__ Cout,
                     int M, int Nn, int K)
{
    __shared__ __align__(128) __half As[3][128*64];   // 48 KB
    __shared__ __align__(128) __half Bs[3][256*64];   // 96 KB
    const __half* A  = (MODE==0) ? g_attnout : g_xr;
    const __half* Bw = (MODE==0) ? g_wr_proj : g_wr_qkv;
    const int tid=threadIdx.x, warp=tid>>5, lane=tid&31;
    const int wm=warp&3, wn=warp>>2;
    const int m0=blockIdx.y*128, n0=blockIdx.x*256;
    const int nT = K >> 6;

    const uint32_t aBase = smem_addr_of(As);
    const uint32_t bBase = smem_addr_of(Bs);

    // fill assignment: A 4 chunks, B 8 chunks of 16 B per thread per tile
    int arow[4], ac[4]; uint32_t adst[4];
#pragma unroll
    for (int u=0; u<4; u++) {
        int f = tid + 256*u;
        arow[u] = f>>3; ac[u] = f&7;
        adst[u] = (uint32_t)(arow[u]*128 + ((ac[u] ^ (arow[u]&7))<<4));
    }
    int brow[8], bc[8]; uint32_t bdst[8];
#pragma unroll
    for (int u=0; u<8; u++) {
        int f = tid + 256*u;
        brow[u] = f>>3; bc[u] = f&7;
        bdst[u] = (uint32_t)(brow[u]*128 + ((bc[u] ^ (brow[u]&7))<<4));
    }

    // ldmatrix per-thread invariants
    const int qa = lane>>3, ra = lane&7;
    int mrow[2];
#pragma unroll
    for (int mt2=0; mt2<2; mt2++)
        mrow[mt2] = (wm*2+mt2)*16 + (qa&1)*8 + ra;
    const int akc = qa>>1;
    const int ntsel = (lane>>4)&1, bkc = (lane>>3)&1;
    int nrow[8];
#pragma unroll
    for (int np2=0; np2<8; np2++)
        nrow[np2] = (wn*16 + np2*2 + ntsel)*8 + ra;

    float acc[2][16][4];
#pragma unroll
    for(int i=0;i<2;i++)
#pragma unroll
        for(int j=0;j<16;j++)
#pragma unroll
            for(int r=0;r<4;r++) acc[i][j][r]=0.f;

    // prologue: fill stages 0, 1
#pragma unroll
    for (int s=0; s<2; s++) {
        int kt = s<<6;
#pragma unroll
        for (int u=0; u<4; u++)
            cp_async16(aBase + s*16384 + adst[u],
                       A + (size_t)(m0+arow[u])*K + kt + ac[u]*8);
#pragma unroll
        for (int u=0; u<8; u++)
            cp_async16(bBase + s*32768 + bdst[u],
                       Bw + (size_t)(n0+brow[u])*K + kt + bc[u]*8);
        cp_commit();
    }

    int cur = 0;
    for (int t=0; t<nT; t++) {
        cp_wait<1>();
        __syncthreads();

        const uint32_t aS = aBase + cur*16384;
        const uint32_t bS = bBase + cur*32768;
#pragma unroll
        for (int ks=0; ks<4; ks++) {
            uint32_t afr[2][4];
#pragma unroll
            for (int mt2=0; mt2<2; mt2++) {
                int m = mrow[mt2];
                int kc = ks*2 + akc;
                ldsm_x4(afr[mt2], aS + m*128 + ((kc ^ (m&7))<<4));
            }
#pragma unroll
            for (int np2=0; np2<8; np2++) {
                int n = nrow[np2];
                int kc = ks*2 + bkc;
                uint32_t bq[4];
                ldsm_x4(bq, bS + n*128 + ((kc ^ (n&7))<<4));
#pragma unroll
                for (int mt2=0; mt2<2; mt2++) {
                    mma_f16(acc[mt2][np2*2+0], afr[mt2], &bq[0]);
                    mma_f16(acc[mt2][np2*2+1], afr[mt2], &bq[2]);
                }
            }
        }

        if (t+2 < nT) {
            int s = cur+2; if (s>=3) s-=3;
            int kt = (t+2)<<6;
#pragma unroll
            for (int u=0; u<4; u++)
                cp_async16(aBase + s*16384 + adst[u],
                           A + (size_t)(m0+arow[u])*K + kt + ac[u]*8);
#pragma unroll
            for (int u=0; u<8; u++)
                cp_async16(bBase + s*32768 + bdst[u],
                           Bw + (size_t)(n0+brow[u])*K + kt + bc[u]*8);
        }
        cp_commit();   // empty group near the tail keeps wait<1> aligned
        if (++cur == 3) cur = 0;
    }

    const int gr=lane>>2, gl=lane&3;
#pragma unroll
    for (int mt2=0; mt2<2; mt2++) {
#pragma unroll
        for (int nt2=0; nt2<16; nt2++) {
            int n = n0 + wn*128 + nt2*8 + gl*2;
            float b0=biasv[n], b1=biasv[n+1];
#pragma unroll
            for (int half_=0; half_<2; half_++) {
                int m = m0 + wm*32 + mt2*16 + gr + half_*8;
                float v0 = acc[mt2][nt2][half_*2+0] + b0;
                float v1 = acc[mt2][nt2][half_*2+1] + b1;
                if (MODE==0) {
                    *(float2*)&Cout[(size_t)m*Nn+n] = make_float2(v0,v1);
                } else {
                    int part=n/DIM, rem=n-part*DIM, h=rem>>6, d=rem&63;
                    int bb=m>>9, tok=m&511;
                    size_t o = ((size_t)((bb*NHEAD+h)*NTOK+tok))*HD + d;
                    if (part==0)      *(uint32_t*)(g_q+o) = pack_h2(v0*ATTN_SCALE, v1*ATTN_SCALE);
                    else if (part==1) *(uint32_t*)(g_k+o) = pack_h2(v0, v1);
                    else              *(uint32_t*)(g_v+o) = pack_h2(v0, v1);
                }
            }
        }
    }
}

// ---- FP16 mma flash attention (unchanged) ----
__global__ __launch_bounds__(256,2)
void attn_mma_kernel()
{
    __shared__ uint32_t Qs[4096];
    __shared__ uint32_t KVs[2048];

    const int tid=threadIdx.x, warp=tid>>5, lane=tid&31, l_l=lane&3;
    const int row0=blockIdx.x*128, h=blockIdx.y, b=blockIdx.z;
    const size_t base = ((size_t)(b*NHEAD+h))*NTOK*HD;
    const int rt = blockIdx.x*8 + warp;

#pragma unroll
    for (int u=0; u<4; u++) {
        int f4=tid+256*u, row=f4>>3, ko=f4&7;
        uint4 q = *(const uint4*)(g_q + base + (size_t)(row0+row)*HD + ko*8);
        int ks=ko>>1, kh=ko&1, mt=row>>4, g=row&7, rh=(row>>3)&1;
        int sg=(ks^(g>>1))&3;
        int ab=(mt*4+ks)*128 + 16*g + rh + 2*kh;
        Qs[ab+4*(0^sg)]=q.x; Qs[ab+4*(1^sg)]=q.y;
        Qs[ab+4*(2^sg)]=q.z; Qs[ab+4*(3^sg)]=q.w;
    }

    float oacc[8][4];
#pragma unroll
    for(int i=0;i<8;i++)
#pragma unroll
        for(int j=0;j<4;j++) oacc[i][j]=0.f;
    float s0=0.f, s1=0.f;

    for (int ch=0; ch<8; ch++) {
        const int c0=ch*64;
        __syncthreads();

#pragma unroll
        for (int u=0; u<2; u++) {
            int f4=tid+256*u, key=f4>>3, ko=f4&7;
            uint4 kv = *(const uint4*)(g_k + base + (size_t)(c0+key)*HD + ko*8);
            int ks=ko>>1, kh=ko&1, nt=key>>3, g=key&7;
            int sg=(((ks^nt)&3)^(g>>1))&3;
            int bb=(nt*4+ks)*64 + 8*g + kh;
            KVs[bb+2*(0^sg)]=kv.x; KVs[bb+2*(1^sg)]=kv.y;
            KVs[bb+2*(2^sg)]=kv.z; KVs[bb+2*(3^sg)]=kv.w;
        }
        __syncthreads();

        float sf[8][4];
#pragma unroll
        for(int i=0;i<8;i++)
#pragma unroll
            for(int j=0;j<4;j++) sf[i][j]=0.f;
#pragma unroll
        for (int ks=0; ks<4; ks++) {
            int sa = lane ^ ((ks^(lane>>3))&3);
            uint32_t a[4];
            *(uint4*)a = *(const uint4*)&Qs[(warp*4+ks)*128 + 4*sa];
#pragma unroll
            for (int nt=0; nt<8; nt++) {
                int sb = lane ^ ((((ks^nt)&3)^(lane>>3))&3);
                uint32_t bb[2];
                *(uint2*)bb = *(const uint2*)&KVs[(nt*4+ks)*64 + 2*sb];
                mma_f16(sf[nt],a,bb);
            }
        }
        __syncthreads();

#pragma unroll
        for (int u=0; u<2; u++) {
            int f4=tid+256*u, key=f4>>3, d0=(f4&7)*8;
            uint4 vv = *(const uint4*)(g_v + base + (size_t)(c0+key)*HD + d0);
            const __half* vh = (const __half*)&vv;
            int nt=d0>>3, kcs=key>>4, reg=(key>>3)&1, l=(key>>1)&3, par=key&1;
            int wb = (nt*4+kcs)*64 + reg;
#pragma unroll
            for (int j=0; j<8; j++) {
                int sg=(((kcs^nt)&3)^(j>>1))&3;
                ((__half*)KVs)[(wb + 8*j + 2*(l^sg))*2 + par] = vh[j];
            }
        }

#pragma unroll
        for (int nt=0; nt<8; nt++) {
            float4 bf = *(const float4*)&g_biasp[
                ((((size_t)h*32+rt)*8+ch)*8+nt)*128 + lane*4];
            sf[nt][0]=__expf(sf[nt][0]+bf.x);
            sf[nt][1]=__expf(sf[nt][1]+bf.y);
            sf[nt][2]=__expf(sf[nt][2]+bf.z);
            sf[nt][3]=__expf(sf[nt][3]+bf.w);
            s0 += sf[nt][0]+sf[nt][1];
            s1 += sf[nt][2]+sf[nt][3];
        }
        __syncthreads();

#pragma unroll
        for (int kcs=0; kcs<4; kcs++) {
            uint32_t a[4];
            a[0] = pack_h2(sf[2*kcs  ][0], sf[2*kcs  ][1]);
            a[1] = pack_h2(sf[2*kcs  ][2], sf[2*kcs  ][3]);
            a[2] = pack_h2(sf[2*kcs+1][0], sf[2*kcs+1][1]);
            a[3] = pack_h2(sf[2*kcs+1][2], sf[2*kcs+1][3]);
#pragma unroll
            for (int nt=0; nt<8; nt++) {
                int sb = lane ^ ((((kcs^nt)&3)^(lane>>3))&3);
                uint32_t bb[2];
                *(uint2*)bb = *(const uint2*)&KVs[(nt*4+kcs)*64 + 2*sb];
                mma_f16(oacc[nt],a,bb);
            }
        }
    }

    s0 += __shfl_xor_sync(0xffffffffu,s0,1);
    s0 += __shfl_xor_sync(0xffffffffu,s0,2);
    s1 += __shfl_xor_sync(0xffffffffu,s1,1);
    s1 += __shfl_xor_sync(0xffffffffu,s1,2);
    float i0=1.f/s0, i1=1.f/s1;
    int rowA = row0 + warp*16 + (lane>>2);
#pragma unroll
    for (int nt=0; nt<8; nt++) {
        int col = h*HD + nt*8 + 2*l_l;
        *(uint32_t*)(g_attnout + ((size_t)b*NTOK+rowA)*DIM + col) =
            pack_h2(oacc[nt][0]*i0, oacc[nt][1]*i0);
        *(uint32_t*)(g_attnout + ((size_t)b*NTOK+rowA+8)*DIM + col) =
            pack_h2(oacc[nt][2]*i1, oacc[nt][3]*i1);
    }
}

extern "C" void kernel_launch(void* const* d_in, const int* in_sizes, int n_in,
                              void* d_out, int out_size)
{
    const float* x     = (const float*)d_in[0];
    const float* Wqkv  = (const float*)d_in[1];
    const float* bqkv  = (const float*)d_in[2];
    const float* table = (const float*)d_in[3];
    const int*   idx   = (const int*)  d_in[4];
    const float* Wproj = (const float*)d_in[5];
    const float* bproj = (const float*)d_in[6];
    float* out = (float*)d_out;

    __half* xr; __half* wqkvr; __half* wprojr;
    cudaGetSymbolAddress((void**)&xr,     g_xr);
    cudaGetSymbolAddress((void**)&wqkvr,  g_wr_qkv);
    cudaGetSymbolAddress((void**)&wprojr, g_wr_proj);

    half_copy_kernel<<<(MTOK*DIM/4 + 255)/256, 256>>>(x, xr, MTOK*DIM/4);
    half_copy_kernel<<<(QKV_N*DIM/4 + 255)/256, 256>>>(Wqkv, wqkvr, QKV_N*DIM/4);
    half_copy_kernel<<<(DIM*DIM/4 + 255)/256, 256>>>(Wproj, wprojr, DIM*DIM/4);

    bias_gather_kernel<<<(NTOK*NTOK)/256, 256>>>(table, idx);

    gemm_f16_kernel<1><<<dim3(QKV_N/256, MTOK/128), 256>>>(bqkv, nullptr,
                                                           MTOK, QKV_N, DIM);

    attn_mma_kernel<<<dim3(NTOK/128, NHEAD, NBATCH), 256>>>();

    gemm_f16_kernel<0><<<dim3(DIM/256, MTOK/128), 256>>>(bproj, out,
                                                         MTOK, DIM, DIM);
}